// round 2
// baseline (speedup 1.0000x reference)
#include <cuda_runtime.h>
#include <cmath>

// Problem constants (fixed by setup_inputs)
#define NG    8192        // total genes
#define BGRP  16          // groups
#define GS    512         // group size
#define DIM   768         // hidden dim

// Scratch (no allocations allowed -> __device__ globals)
__device__ float g_Q[NG * DIM];
__device__ float g_K[NG * DIM];
__device__ float g_V[NG * DIM];
__device__ float g_S[BGRP * GS * GS];   // scores / probs (in-place softmax)
__device__ float g_DYN[NG * DIM];

// ---------------------------------------------------------------------------
// GEMM NT: C[M,N] = A[M,K] @ B[N,K]^T  (both row-major, K contiguous)
// MODE 0: C = acc + bias[n]                      (QKV projections)
// MODE 1: C = acc * scale                        (scores, batched over z)
// MODE 2: C = X + beta[0] * (acc + bias[n])      (output projection + residual)
// Tiles: BM=BN=128, BK=16, 256 threads, 8x8 per thread. All dims divide evenly.
// ---------------------------------------------------------------------------
template <int MODE>
__global__ __launch_bounds__(256)
void gemm_nt(const float* __restrict__ A, const float* __restrict__ B,
             const float* __restrict__ bias, float* __restrict__ C,
             int K, int lda, int ldb, int ldc,
             long strideA, long strideB, long strideC,
             float scale,
             const float* __restrict__ X, const float* __restrict__ beta)
{
    const int BM = 128, BN = 128, BK = 16, TM = 8, TN = 8;
    __shared__ float As[BK][BM];
    __shared__ float Bs[BK][BN];

    const int bz = blockIdx.z;
    A += bz * strideA;  B += bz * strideB;  C += bz * strideC;

    const int row0 = blockIdx.y * BM;
    const int col0 = blockIdx.x * BN;
    const int tid = threadIdx.x;
    const int tx = tid & 15;        // 16 thread-cols
    const int ty = tid >> 4;        // 16 thread-rows

    float acc[TM][TN];
#pragma unroll
    for (int i = 0; i < TM; i++)
#pragma unroll
        for (int j = 0; j < TN; j++) acc[i][j] = 0.f;

    for (int k0 = 0; k0 < K; k0 += BK) {
        // Load A tile: 128x16 floats = 512 float4 (2 per thread), store transposed
#pragma unroll
        for (int i = 0; i < 2; i++) {
            int idx = tid + i * 256;
            int r = idx >> 2, c4 = (idx & 3) << 2;
            float4 v = *(const float4*)(A + (long)(row0 + r) * lda + k0 + c4);
            As[c4 + 0][r] = v.x; As[c4 + 1][r] = v.y;
            As[c4 + 2][r] = v.z; As[c4 + 3][r] = v.w;
        }
        // Load B tile: 128x16 floats, transposed
#pragma unroll
        for (int i = 0; i < 2; i++) {
            int idx = tid + i * 256;
            int r = idx >> 2, c4 = (idx & 3) << 2;
            float4 v = *(const float4*)(B + (long)(col0 + r) * ldb + k0 + c4);
            Bs[c4 + 0][r] = v.x; Bs[c4 + 1][r] = v.y;
            Bs[c4 + 2][r] = v.z; Bs[c4 + 3][r] = v.w;
        }
        __syncthreads();

#pragma unroll
        for (int kk = 0; kk < BK; kk++) {
            float a[TM], b[TN];
            float4 a0 = *(const float4*)&As[kk][ty * TM];
            float4 a1 = *(const float4*)&As[kk][ty * TM + 4];
            a[0]=a0.x; a[1]=a0.y; a[2]=a0.z; a[3]=a0.w;
            a[4]=a1.x; a[5]=a1.y; a[6]=a1.z; a[7]=a1.w;
            float4 b0 = *(const float4*)&Bs[kk][tx * TN];
            float4 b1 = *(const float4*)&Bs[kk][tx * TN + 4];
            b[0]=b0.x; b[1]=b0.y; b[2]=b0.z; b[3]=b0.w;
            b[4]=b1.x; b[5]=b1.y; b[6]=b1.z; b[7]=b1.w;
#pragma unroll
            for (int i = 0; i < TM; i++)
#pragma unroll
                for (int j = 0; j < TN; j++)
                    acc[i][j] = fmaf(a[i], b[j], acc[i][j]);
        }
        __syncthreads();
    }

    // Epilogue
    float betav = 0.f;
    if (MODE == 2) betav = beta[0];

#pragma unroll
    for (int i = 0; i < TM; i++) {
        int r = row0 + ty * TM + i;
#pragma unroll
        for (int jj = 0; jj < TN; jj += 4) {
            int c = col0 + tx * TN + jj;
            float4 v;
            v.x = acc[i][jj + 0]; v.y = acc[i][jj + 1];
            v.z = acc[i][jj + 2]; v.w = acc[i][jj + 3];
            if (MODE == 0) {
                v.x += bias[c + 0]; v.y += bias[c + 1];
                v.z += bias[c + 2]; v.w += bias[c + 3];
            } else if (MODE == 1) {
                v.x *= scale; v.y *= scale; v.z *= scale; v.w *= scale;
            } else {
                const float4 xb = *(const float4*)(X + (long)r * ldc + c);
                v.x = xb.x + betav * (v.x + bias[c + 0]);
                v.y = xb.y + betav * (v.y + bias[c + 1]);
                v.z = xb.z + betav * (v.z + bias[c + 2]);
                v.w = xb.w + betav * (v.w + bias[c + 3]);
            }
            *(float4*)(C + (long)r * ldc + c) = v;
        }
    }
}

// ---------------------------------------------------------------------------
// GEMM NN: C[M,N] = A[M,K] @ B[K,N]   (P @ V, batched over z)
// ---------------------------------------------------------------------------
__global__ __launch_bounds__(256)
void gemm_nn(const float* __restrict__ A, const float* __restrict__ B,
             float* __restrict__ C,
             int K, int lda, int ldb, int ldc,
             long strideA, long strideB, long strideC)
{
    const int BM = 128, BN = 128, BK = 16, TM = 8, TN = 8;
    __shared__ float As[BK][BM];
    __shared__ float Bs[BK][BN];

    const int bz = blockIdx.z;
    A += bz * strideA;  B += bz * strideB;  C += bz * strideC;

    const int row0 = blockIdx.y * BM;
    const int col0 = blockIdx.x * BN;
    const int tid = threadIdx.x;
    const int tx = tid & 15;
    const int ty = tid >> 4;

    float acc[TM][TN];
#pragma unroll
    for (int i = 0; i < TM; i++)
#pragma unroll
        for (int j = 0; j < TN; j++) acc[i][j] = 0.f;

    for (int k0 = 0; k0 < K; k0 += BK) {
        // A tile (transposed into smem)
#pragma unroll
        for (int i = 0; i < 2; i++) {
            int idx = tid + i * 256;
            int r = idx >> 2, c4 = (idx & 3) << 2;
            float4 v = *(const float4*)(A + (long)(row0 + r) * lda + k0 + c4);
            As[c4 + 0][r] = v.x; As[c4 + 1][r] = v.y;
            As[c4 + 2][r] = v.z; As[c4 + 3][r] = v.w;
        }
        // B tile: [BK rows x BN cols], direct layout, coalesced along N
#pragma unroll
        for (int i = 0; i < 2; i++) {
            int idx = tid + i * 256;
            int r = idx >> 5, c4 = (idx & 31) << 2;
            float4 v = *(const float4*)(B + (long)(k0 + r) * ldb + col0 + c4);
            *(float4*)&Bs[r][c4] = v;
        }
        __syncthreads();

#pragma unroll
        for (int kk = 0; kk < BK; kk++) {
            float a[TM], b[TN];
            float4 a0 = *(const float4*)&As[kk][ty * TM];
            float4 a1 = *(const float4*)&As[kk][ty * TM + 4];
            a[0]=a0.x; a[1]=a0.y; a[2]=a0.z; a[3]=a0.w;
            a[4]=a1.x; a[5]=a1.y; a[6]=a1.z; a[7]=a1.w;
            float4 b0 = *(const float4*)&Bs[kk][tx * TN];
            float4 b1 = *(const float4*)&Bs[kk][tx * TN + 4];
            b[0]=b0.x; b[1]=b0.y; b[2]=b0.z; b[3]=b0.w;
            b[4]=b1.x; b[5]=b1.y; b[6]=b1.z; b[7]=b1.w;
#pragma unroll
            for (int i = 0; i < TM; i++)
#pragma unroll
                for (int j = 0; j < TN; j++)
                    acc[i][j] = fmaf(a[i], b[j], acc[i][j]);
        }
        __syncthreads();
    }

#pragma unroll
    for (int i = 0; i < TM; i++) {
        int r = row0 + ty * TM + i;
#pragma unroll
        for (int jj = 0; jj < TN; jj += 4) {
            int c = col0 + tx * TN + jj;
            float4 v;
            v.x = acc[i][jj + 0]; v.y = acc[i][jj + 1];
            v.z = acc[i][jj + 2]; v.w = acc[i][jj + 3];
            *(float4*)(C + (long)r * ldc + c) = v;
        }
    }
}

// ---------------------------------------------------------------------------
// Row softmax over group (512 keys), diagonal self-masked. In-place on g_S.
// One CTA (128 threads) per row; 4 elements per thread.
// ---------------------------------------------------------------------------
__global__ __launch_bounds__(128)
void softmax_rows(float* __restrict__ S)
{
    const int row = blockIdx.x;            // 0..8191
    const int g = row >> 9;
    const int r = row & 511;
    float* p = S + ((long)g << 18) + ((long)r << 9);
    const int tid = threadIdx.x;
    const int w = tid >> 5, l = tid & 31;

    float v[4];
    float mx = -INFINITY;
#pragma unroll
    for (int i = 0; i < 4; i++) {
        int j = tid + (i << 7);
        float t = p[j];
        if (j == r) t = -INFINITY;          // self mask
        v[i] = t;
        mx = fmaxf(mx, t);
    }
#pragma unroll
    for (int o = 16; o; o >>= 1) mx = fmaxf(mx, __shfl_xor_sync(0xffffffffu, mx, o));
    __shared__ float sm[4], ss[4];
    if (l == 0) sm[w] = mx;
    __syncthreads();
    mx = fmaxf(fmaxf(sm[0], sm[1]), fmaxf(sm[2], sm[3]));

    float sum = 0.f;
#pragma unroll
    for (int i = 0; i < 4; i++) { v[i] = __expf(v[i] - mx); sum += v[i]; }
#pragma unroll
    for (int o = 16; o; o >>= 1) sum += __shfl_xor_sync(0xffffffffu, sum, o);
    if (l == 0) ss[w] = sum;
    __syncthreads();
    sum = ss[0] + ss[1] + ss[2] + ss[3];
    const float inv = 1.f / sum;
#pragma unroll
    for (int i = 0; i < 4; i++) p[tid + (i << 7)] = v[i] * inv;
}

// ---------------------------------------------------------------------------
// Launcher
// Inputs (metadata order): gene_embeddings, batch(int64, unused — groups are
// contiguous 512), Wq, bq, Wk, bk, Wv, bv, Wo, bo, beta.
// ---------------------------------------------------------------------------
extern "C" void kernel_launch(void* const* d_in, const int* in_sizes, int n_in,
                              void* d_out, int out_size)
{
    (void)in_sizes; (void)n_in; (void)out_size;
    const float* x    = (const float*)d_in[0];
    const float* Wq   = (const float*)d_in[2];
    const float* bq   = (const float*)d_in[3];
    const float* Wk   = (const float*)d_in[4];
    const float* bk   = (const float*)d_in[5];
    const float* Wv   = (const float*)d_in[6];
    const float* bv   = (const float*)d_in[7];
    const float* Wo   = (const float*)d_in[8];
    const float* bo   = (const float*)d_in[9];
    const float* beta = (const float*)d_in[10];
    float* out = (float*)d_out;

    float *Q, *K, *V, *S, *DYN;
    cudaGetSymbolAddress((void**)&Q,   g_Q);
    cudaGetSymbolAddress((void**)&K,   g_K);
    cudaGetSymbolAddress((void**)&V,   g_V);
    cudaGetSymbolAddress((void**)&S,   g_S);
    cudaGetSymbolAddress((void**)&DYN, g_DYN);

    const dim3 blk(256);
    const float scale = 1.0f / sqrtf((float)DIM);

    // Q/K/V projections: [8192,768] @ [768,768]^T + bias
    gemm_nt<0><<<dim3(6, 64, 1), blk>>>(x, Wq, bq, Q, DIM, DIM, DIM, DIM,
                                        0, 0, 0, 1.f, nullptr, nullptr);
    gemm_nt<0><<<dim3(6, 64, 1), blk>>>(x, Wk, bk, K, DIM, DIM, DIM, DIM,
                                        0, 0, 0, 1.f, nullptr, nullptr);
    gemm_nt<0><<<dim3(6, 64, 1), blk>>>(x, Wv, bv, V, DIM, DIM, DIM, DIM,
                                        0, 0, 0, 1.f, nullptr, nullptr);

    // Per-group scores: S_g = Q_g @ K_g^T * scale   (batched z=16)
    gemm_nt<1><<<dim3(4, 4, BGRP), blk>>>(Q, K, nullptr, S, DIM, DIM, DIM, GS,
                                          (long)GS * DIM, (long)GS * DIM,
                                          (long)GS * GS, scale, nullptr, nullptr);

    // Masked softmax per row (in place)
    softmax_rows<<<NG, 128>>>(S);

    // Per-group P @ V  (batched z=16)
    gemm_nn<<<dim3(6, 4, BGRP), blk>>>(S, V, DYN, GS, GS, DIM, DIM,
                                       (long)GS * GS, (long)GS * DIM,
                                       (long)GS * DIM);

    // Output projection + residual: out = x + beta*(DYN @ Wo^T + bo)
    gemm_nt<2><<<dim3(6, 64, 1), blk>>>(DYN, Wo, bo, out, DIM, DIM, DIM, DIM,
                                        0, 0, 0, 1.f, x, beta);
}

// round 4
// speedup vs baseline: 6.1800x; 6.1800x over previous
#include <cuda_runtime.h>
#include <cuda_bf16.h>
#include <cstdint>
#include <cmath>

#define NG    8192
#define BGRP  16
#define GS    512
#define DIM   768

// tile sizes
#define TBM 128
#define TBN 128
#define TBK 32

// ---------------- scratch (device globals; no allocs allowed) ----------------
__device__ __nv_bfloat16 g_xb [NG * DIM];
__device__ __nv_bfloat16 g_Wqb[DIM * DIM];
__device__ __nv_bfloat16 g_Wkb[DIM * DIM];
__device__ __nv_bfloat16 g_Wvb[DIM * DIM];
__device__ __nv_bfloat16 g_Wob[DIM * DIM];
__device__ __nv_bfloat16 g_Q  [NG * DIM];
__device__ __nv_bfloat16 g_K  [NG * DIM];
__device__ __nv_bfloat16 g_V  [NG * DIM];
__device__ float         g_S  [BGRP * GS * GS];
__device__ __nv_bfloat16 g_P  [BGRP * GS * GS];
__device__ __nv_bfloat16 g_DYN[NG * DIM];

// ---------------- helpers ----------------
__device__ __forceinline__ unsigned sptr(const void* p) {
    return (unsigned)__cvta_generic_to_shared(p);
}
__device__ __forceinline__ void cpasync16(unsigned s, const void* g) {
    asm volatile("cp.async.cg.shared.global [%0], [%1], 16;\n" :: "r"(s), "l"(g));
}
__device__ __forceinline__ void cp_commit() {
    asm volatile("cp.async.commit_group;\n" ::: "memory");
}
__device__ __forceinline__ void cp_wait1() {
    asm volatile("cp.async.wait_group 1;\n" ::: "memory");
}
__device__ __forceinline__ void ldsm4(unsigned& r0, unsigned& r1, unsigned& r2, unsigned& r3, unsigned a) {
    asm volatile("ldmatrix.sync.aligned.m8n8.x4.shared.b16 {%0,%1,%2,%3}, [%4];\n"
                 : "=r"(r0), "=r"(r1), "=r"(r2), "=r"(r3) : "r"(a));
}
__device__ __forceinline__ void ldsm4t(unsigned& r0, unsigned& r1, unsigned& r2, unsigned& r3, unsigned a) {
    asm volatile("ldmatrix.sync.aligned.m8n8.x4.trans.shared.b16 {%0,%1,%2,%3}, [%4];\n"
                 : "=r"(r0), "=r"(r1), "=r"(r2), "=r"(r3) : "r"(a));
}
__device__ __forceinline__ void mma16816(float* d, const unsigned* a, const unsigned* b) {
    asm volatile(
        "mma.sync.aligned.m16n8k16.row.col.f32.bf16.bf16.f32 "
        "{%0,%1,%2,%3}, {%4,%5,%6,%7}, {%8,%9}, {%0,%1,%2,%3};\n"
        : "+f"(d[0]), "+f"(d[1]), "+f"(d[2]), "+f"(d[3])
        : "r"(a[0]), "r"(a[1]), "r"(a[2]), "r"(a[3]), "r"(b[0]), "r"(b[1]));
}

// ---------------- fp32 -> bf16 convert ----------------
__global__ __launch_bounds__(256)
void f2bf(const float* __restrict__ in, __nv_bfloat16* __restrict__ out, int n) {
    int i = (blockIdx.x * 256 + threadIdx.x) * 4;
    if (i < n) {
        float4 v = *reinterpret_cast<const float4*>(in + i);
        *reinterpret_cast<__nv_bfloat162*>(out + i)     = __floats2bfloat162_rn(v.x, v.y);
        *reinterpret_cast<__nv_bfloat162*>(out + i + 2) = __floats2bfloat162_rn(v.z, v.w);
    }
}

// ---- cp.async tile issue (A tile always k-contiguous; B depends on TB) ----
template<bool TB>
__device__ __forceinline__ void issue_tile(
    const __nv_bfloat16* __restrict__ A, const __nv_bfloat16* __restrict__ B,
    __nv_bfloat16* As, __nv_bfloat16* Bs,
    int row0, int col0, int lda, int ldb, int kt, int tid)
{
#pragma unroll
    for (int i = 0; i < 2; i++) {
        int lin = tid + i * 256;
        int r = lin >> 2, c = lin & 3;
        const __nv_bfloat16* g = A + (long)(row0 + r) * lda + kt * TBK + c * 8;
        cpasync16(sptr(As + r * TBK + ((c ^ ((r >> 1) & 3)) << 3)), g);
    }
    if (!TB) {
#pragma unroll
        for (int i = 0; i < 2; i++) {
            int lin = tid + i * 256;
            int r = lin >> 2, c = lin & 3;
            const __nv_bfloat16* g = B + (long)(col0 + r) * ldb + kt * TBK + c * 8;
            cpasync16(sptr(Bs + r * TBK + ((c ^ ((r >> 1) & 3)) << 3)), g);
        }
    } else {
#pragma unroll
        for (int i = 0; i < 2; i++) {
            int lin = tid + i * 256;
            int r = lin >> 4, c = lin & 15;
            const __nv_bfloat16* g = B + (long)(kt * TBK + r) * ldb + col0 + c * 8;
            cpasync16(sptr(Bs + r * TBN + ((c ^ (r & 7)) << 3)), g);
        }
    }
}

// ---------------------------------------------------------------------------
// bf16 tensor-core GEMM: C[M,N] = A[M,K] @ op(B)
//   TB=false: B is [N,K] row-major (k-contiguous)  -> C = A @ B^T   (NT)
//   TB=true : B is [K,N] row-major (n-contiguous)  -> C = A @ B     (NN)
// MODE 0: bf16 C = acc + bias[n]
// MODE 1: fp32 C = acc * scale
// MODE 2: bf16 C = acc
// MODE 3: fp32 C = X + beta[0] * (acc + bias[n])
// 128x128x32 tiles, 256 threads (8 warps 2x4), warp tile 64x32,
// 2-stage cp.async pipeline, swizzled smem, ldmatrix + mma.m16n8k16.
// ---------------------------------------------------------------------------
template<int MODE, bool TB>
__global__ __launch_bounds__(256, 2)
void hgemm(const __nv_bfloat16* __restrict__ A, const __nv_bfloat16* __restrict__ B,
           const float* __restrict__ bias, void* __restrict__ Cv,
           int K, int lda, int ldb, int ldc,
           long sA, long sB, long sC,
           float scale, const float* __restrict__ X, const float* __restrict__ beta)
{
    __shared__ __nv_bfloat16 As[2][TBM * TBK];
    __shared__ __nv_bfloat16 Bs[2][TBK * TBN];

    const int bz = blockIdx.z;
    A += bz * sA;
    B += bz * sB;

    const int row0 = blockIdx.y * TBM;
    const int col0 = blockIdx.x * TBN;
    const int tid  = threadIdx.x;
    const int lane = tid & 31;
    const int wid  = tid >> 5;
    const int wm   = (wid & 1) * 64;
    const int wn   = (wid >> 1) * 32;

    float acc[4][4][4];
#pragma unroll
    for (int i = 0; i < 4; i++)
#pragma unroll
        for (int j = 0; j < 4; j++)
#pragma unroll
            for (int k = 0; k < 4; k++) acc[i][j][k] = 0.f;

    const int ntiles = K / TBK;

    issue_tile<TB>(A, B, As[0], Bs[0], row0, col0, lda, ldb, 0, tid);
    cp_commit();

    for (int kt = 0; kt < ntiles; kt++) {
        const int stg = kt & 1;
        if (kt + 1 < ntiles)
            issue_tile<TB>(A, B, As[stg ^ 1], Bs[stg ^ 1], row0, col0, lda, ldb, kt + 1, tid);
        cp_commit();
        cp_wait1();
        __syncthreads();

#pragma unroll
        for (int ks = 0; ks < 2; ks++) {
            unsigned aF[4][4], bF[4][2];
#pragma unroll
            for (int mi = 0; mi < 4; mi++) {
                int r = wm + mi * 16 + (lane & 15);
                int c = ks * 2 + (lane >> 4);
                ldsm4(aF[mi][0], aF[mi][1], aF[mi][2], aF[mi][3],
                      sptr(&As[stg][r * TBK + ((c ^ ((r >> 1) & 3)) << 3)]));
            }
            if (!TB) {
#pragma unroll
                for (int nt = 0; nt < 2; nt++) {
                    int r = wn + nt * 16 + (lane & 15);
                    int c = ks * 2 + (lane >> 4);
                    unsigned r0, r1, r2, r3;
                    ldsm4(r0, r1, r2, r3,
                          sptr(&Bs[stg][r * TBK + ((c ^ ((r >> 1) & 3)) << 3)]));
                    bF[nt * 2 + 0][0] = r0; bF[nt * 2 + 0][1] = r2;
                    bF[nt * 2 + 1][0] = r1; bF[nt * 2 + 1][1] = r3;
                }
            } else {
#pragma unroll
                for (int nt = 0; nt < 2; nt++) {
                    int r = ks * 16 + (lane & 15);
                    int c = (wn >> 3) + nt * 2 + (lane >> 4);
                    unsigned r0, r1, r2, r3;
                    ldsm4t(r0, r1, r2, r3,
                           sptr(&Bs[stg][r * TBN + ((c ^ (r & 7)) << 3)]));
                    bF[nt * 2 + 0][0] = r0; bF[nt * 2 + 0][1] = r1;
                    bF[nt * 2 + 1][0] = r2; bF[nt * 2 + 1][1] = r3;
                }
            }
#pragma unroll
            for (int mi = 0; mi < 4; mi++)
#pragma unroll
                for (int nj = 0; nj < 4; nj++)
                    mma16816(acc[mi][nj], aF[mi], bF[nj]);
        }
        __syncthreads();
    }

    // ---------------- epilogue ----------------
    const int rg = lane >> 2;
    const int t  = lane & 3;
    float betav = 0.f;
    if (MODE == 3) betav = beta[0];

#pragma unroll
    for (int mi = 0; mi < 4; mi++) {
#pragma unroll
        for (int nj = 0; nj < 4; nj++) {
            const int r = row0 + wm + mi * 16 + rg;
            const int c = col0 + wn + nj * 8 + t * 2;
            const float d0 = acc[mi][nj][0];
            const float d1 = acc[mi][nj][1];
            const float d2 = acc[mi][nj][2];
            const float d3 = acc[mi][nj][3];

            if (MODE == 0) {
                __nv_bfloat16* C = reinterpret_cast<__nv_bfloat16*>(Cv) + bz * sC;
                const float2 bb = *reinterpret_cast<const float2*>(bias + c);
                *reinterpret_cast<__nv_bfloat162*>(C + (long)r * ldc + c) =
                    __floats2bfloat162_rn(d0 + bb.x, d1 + bb.y);
                *reinterpret_cast<__nv_bfloat162*>(C + (long)(r + 8) * ldc + c) =
                    __floats2bfloat162_rn(d2 + bb.x, d3 + bb.y);
            } else if (MODE == 1) {
                float* C = reinterpret_cast<float*>(Cv) + bz * sC;
                *reinterpret_cast<float2*>(C + (long)r * ldc + c) =
                    make_float2(d0 * scale, d1 * scale);
                *reinterpret_cast<float2*>(C + (long)(r + 8) * ldc + c) =
                    make_float2(d2 * scale, d3 * scale);
            } else if (MODE == 2) {
                __nv_bfloat16* C = reinterpret_cast<__nv_bfloat16*>(Cv) + bz * sC;
                *reinterpret_cast<__nv_bfloat162*>(C + (long)r * ldc + c) =
                    __floats2bfloat162_rn(d0, d1);
                *reinterpret_cast<__nv_bfloat162*>(C + (long)(r + 8) * ldc + c) =
                    __floats2bfloat162_rn(d2, d3);
            } else {
                float* C = reinterpret_cast<float*>(Cv) + bz * sC;
                const float2 bb = *reinterpret_cast<const float2*>(bias + c);
                const float2 x0 = *reinterpret_cast<const float2*>(X + (long)r * ldc + c);
                const float2 x1 = *reinterpret_cast<const float2*>(X + (long)(r + 8) * ldc + c);
                *reinterpret_cast<float2*>(C + (long)r * ldc + c) =
                    make_float2(x0.x + betav * (d0 + bb.x), x0.y + betav * (d1 + bb.y));
                *reinterpret_cast<float2*>(C + (long)(r + 8) * ldc + c) =
                    make_float2(x1.x + betav * (d2 + bb.x), x1.y + betav * (d3 + bb.y));
            }
        }
    }
}

// ---------------------------------------------------------------------------
// Masked softmax over 512 keys per row (diag self-mask), fp32 in -> bf16 out.
// ---------------------------------------------------------------------------
__global__ __launch_bounds__(128)
void softmax_rows(const float* __restrict__ S, __nv_bfloat16* __restrict__ P)
{
    const int row = blockIdx.x;
    const int grp = row >> 9;
    const int r   = row & 511;
    const float* p = S + ((long)grp << 18) + ((long)r << 9);
    __nv_bfloat16* q = P + ((long)grp << 18) + ((long)r << 9);
    const int tid = threadIdx.x;
    const int w = tid >> 5;
    const int l = tid & 31;
    const int base = tid * 4;

    float4 v4 = *reinterpret_cast<const float4*>(p + base);
    float v0 = v4.x, v1 = v4.y, v2 = v4.z, v3 = v4.w;
    if (base + 0 == r) v0 = -INFINITY;
    if (base + 1 == r) v1 = -INFINITY;
    if (base + 2 == r) v2 = -INFINITY;
    if (base + 3 == r) v3 = -INFINITY;

    float mx = fmaxf(fmaxf(v0, v1), fmaxf(v2, v3));
#pragma unroll
    for (int o = 16; o; o >>= 1) mx = fmaxf(mx, __shfl_xor_sync(0xffffffffu, mx, o));
    __shared__ float sred[8];
    if (l == 0) sred[w] = mx;
    __syncthreads();
    mx = fmaxf(fmaxf(sred[0], sred[1]), fmaxf(sred[2], sred[3]));

    v0 = __expf(v0 - mx); v1 = __expf(v1 - mx);
    v2 = __expf(v2 - mx); v3 = __expf(v3 - mx);
    float sum = v0 + v1 + v2 + v3;
#pragma unroll
    for (int o = 16; o; o >>= 1) sum += __shfl_xor_sync(0xffffffffu, sum, o);
    __syncthreads();
    if (l == 0) sred[4 + w] = sum;
    __syncthreads();
    sum = sred[4] + sred[5] + sred[6] + sred[7];
    const float inv = 1.f / sum;

    *reinterpret_cast<__nv_bfloat162*>(q + base)     = __floats2bfloat162_rn(v0 * inv, v1 * inv);
    *reinterpret_cast<__nv_bfloat162*>(q + base + 2) = __floats2bfloat162_rn(v2 * inv, v3 * inv);
}

// ---------------------------------------------------------------------------
// Launcher. Inputs: x, batch(unused), Wq,bq, Wk,bk, Wv,bv, Wo,bo, beta.
// ---------------------------------------------------------------------------
extern "C" void kernel_launch(void* const* d_in, const int* in_sizes, int n_in,
                              void* d_out, int out_size)
{
    (void)in_sizes; (void)n_in; (void)out_size;
    const float* x    = (const float*)d_in[0];
    const float* Wq   = (const float*)d_in[2];
    const float* bq   = (const float*)d_in[3];
    const float* Wk   = (const float*)d_in[4];
    const float* bk   = (const float*)d_in[5];
    const float* Wv   = (const float*)d_in[6];
    const float* bv   = (const float*)d_in[7];
    const float* Wo   = (const float*)d_in[8];
    const float* bo   = (const float*)d_in[9];
    const float* beta = (const float*)d_in[10];
    float* out = (float*)d_out;

    __nv_bfloat16 *xb, *Wqb, *Wkb, *Wvb, *Wob, *Q, *K, *V, *P, *DYN;
    float *S;
    cudaGetSymbolAddress((void**)&xb,  g_xb);
    cudaGetSymbolAddress((void**)&Wqb, g_Wqb);
    cudaGetSymbolAddress((void**)&Wkb, g_Wkb);
    cudaGetSymbolAddress((void**)&Wvb, g_Wvb);
    cudaGetSymbolAddress((void**)&Wob, g_Wob);
    cudaGetSymbolAddress((void**)&Q,   g_Q);
    cudaGetSymbolAddress((void**)&K,   g_K);
    cudaGetSymbolAddress((void**)&V,   g_V);
    cudaGetSymbolAddress((void**)&S,   g_S);
    cudaGetSymbolAddress((void**)&P,   g_P);
    cudaGetSymbolAddress((void**)&DYN, g_DYN);

    const float scale = 1.0f / sqrtf((float)DIM);
    const dim3 blk(256);

    // fp32 -> bf16 converts
    f2bf<<<NG * DIM / 1024, 256>>>(x,  xb,  NG * DIM);
    f2bf<<<DIM * DIM / 1024, 256>>>(Wq, Wqb, DIM * DIM);
    f2bf<<<DIM * DIM / 1024, 256>>>(Wk, Wkb, DIM * DIM);
    f2bf<<<DIM * DIM / 1024, 256>>>(Wv, Wvb, DIM * DIM);
    f2bf<<<DIM * DIM / 1024, 256>>>(Wo, Wob, DIM * DIM);

    // QKV projections: bf16 [8192,768] @ [768,768]^T + bias -> bf16
    hgemm<0, false><<<dim3(6, 64, 1), blk>>>(xb, Wqb, bq, Q, DIM, DIM, DIM, DIM,
                                             0, 0, 0, 1.f, nullptr, nullptr);
    hgemm<0, false><<<dim3(6, 64, 1), blk>>>(xb, Wkb, bk, K, DIM, DIM, DIM, DIM,
                                             0, 0, 0, 1.f, nullptr, nullptr);
    hgemm<0, false><<<dim3(6, 64, 1), blk>>>(xb, Wvb, bv, V, DIM, DIM, DIM, DIM,
                                             0, 0, 0, 1.f, nullptr, nullptr);

    // Per-group scores: S_g = Q_g @ K_g^T * scale (fp32 out, batched z=16)
    hgemm<1, false><<<dim3(4, 4, BGRP), blk>>>(Q, K, nullptr, S, DIM, DIM, DIM, GS,
                                               (long)GS * DIM, (long)GS * DIM,
                                               (long)GS * GS, scale, nullptr, nullptr);

    // Masked softmax: fp32 S -> bf16 P
    softmax_rows<<<NG, 128>>>(S, P);

    // Per-group P @ V -> bf16 DYN (NN via ldmatrix.trans, batched z=16)
    hgemm<2, true><<<dim3(6, 4, BGRP), blk>>>(P, V, nullptr, DYN, GS, GS, DIM, DIM,
                                              (long)GS * GS, (long)GS * DIM,
                                              (long)GS * DIM, 1.f, nullptr, nullptr);

    // Output projection + residual: out = x + beta*(DYN @ Wo^T + bo) (fp32)
    hgemm<3, false><<<dim3(6, 64, 1), blk>>>(DYN, Wob, bo, out, DIM, DIM, DIM, DIM,
                                             0, 0, 0, 1.f, x, beta);
}

// round 6
// speedup vs baseline: 6.6768x; 1.0804x over previous
#include <cuda_runtime.h>
#include <cuda_bf16.h>
#include <cstdint>
#include <cmath>

#define NG    8192
#define BGRP  16
#define GS    512
#define DIM   768

// tile sizes
#define TBM 128
#define TBN 128
#define TBK 32
#define NSTAGE 3
#define STAGE_ELEMS (TBM * TBK)                  // per-operand per-stage bf16 elems
#define SMEM_BYTES (NSTAGE * 2 * STAGE_ELEMS * 2) // 49152 bytes

// ---------------- scratch (device globals; no allocs allowed) ----------------
__device__ __nv_bfloat16 g_xb [NG * DIM];
__device__ __nv_bfloat16 g_Wqb[DIM * DIM];
__device__ __nv_bfloat16 g_Wkb[DIM * DIM];
__device__ __nv_bfloat16 g_Wvb[DIM * DIM];
__device__ __nv_bfloat16 g_Wob[DIM * DIM];
__device__ __nv_bfloat16 g_Q  [NG * DIM];
__device__ __nv_bfloat16 g_K  [NG * DIM];
__device__ __nv_bfloat16 g_V  [NG * DIM];
__device__ float         g_S  [BGRP * GS * GS];
__device__ __nv_bfloat16 g_P  [BGRP * GS * GS];
__device__ __nv_bfloat16 g_DYN[NG * DIM];

// ---------------- helpers ----------------
__device__ __forceinline__ unsigned sptr(const void* p) {
    return (unsigned)__cvta_generic_to_shared(p);
}
__device__ __forceinline__ void cpasync16(unsigned s, const void* g) {
    asm volatile("cp.async.cg.shared.global [%0], [%1], 16;\n" :: "r"(s), "l"(g));
}
__device__ __forceinline__ void cp_commit() {
    asm volatile("cp.async.commit_group;\n" ::: "memory");
}
__device__ __forceinline__ void cp_wait2() {
    asm volatile("cp.async.wait_group 2;\n" ::: "memory");
}
__device__ __forceinline__ void ldsm4(unsigned& r0, unsigned& r1, unsigned& r2, unsigned& r3, unsigned a) {
    asm volatile("ldmatrix.sync.aligned.m8n8.x4.shared.b16 {%0,%1,%2,%3}, [%4];\n"
                 : "=r"(r0), "=r"(r1), "=r"(r2), "=r"(r3) : "r"(a));
}
__device__ __forceinline__ void ldsm4t(unsigned& r0, unsigned& r1, unsigned& r2, unsigned& r3, unsigned a) {
    asm volatile("ldmatrix.sync.aligned.m8n8.x4.trans.shared.b16 {%0,%1,%2,%3}, [%4];\n"
                 : "=r"(r0), "=r"(r1), "=r"(r2), "=r"(r3) : "r"(a));
}
__device__ __forceinline__ void mma16816(float* d, const unsigned* a, const unsigned* b) {
    asm volatile(
        "mma.sync.aligned.m16n8k16.row.col.f32.bf16.bf16.f32 "
        "{%0,%1,%2,%3}, {%4,%5,%6,%7}, {%8,%9}, {%0,%1,%2,%3};\n"
        : "+f"(d[0]), "+f"(d[1]), "+f"(d[2]), "+f"(d[3])
        : "r"(a[0]), "r"(a[1]), "r"(a[2]), "r"(a[3]), "r"(b[0]), "r"(b[1]));
}

// ---- cp.async tile issue into stage buffers ----
template<bool TB>
__device__ __forceinline__ void issue_tile(
    const __nv_bfloat16* __restrict__ A, const __nv_bfloat16* __restrict__ B,
    __nv_bfloat16* As, __nv_bfloat16* Bs,
    int row0, int col0, int lda, int ldb, int kt, int tid)
{
#pragma unroll
    for (int i = 0; i < 2; i++) {
        int lin = tid + i * 256;
        int r = lin >> 2, c = lin & 3;
        const __nv_bfloat16* g = A + (long)(row0 + r) * lda + kt * TBK + c * 8;
        cpasync16(sptr(As + r * TBK + ((c ^ ((r >> 1) & 3)) << 3)), g);
    }
    if (!TB) {
#pragma unroll
        for (int i = 0; i < 2; i++) {
            int lin = tid + i * 256;
            int r = lin >> 2, c = lin & 3;
            const __nv_bfloat16* g = B + (long)(col0 + r) * ldb + kt * TBK + c * 8;
            cpasync16(sptr(Bs + r * TBK + ((c ^ ((r >> 1) & 3)) << 3)), g);
        }
    } else {
#pragma unroll
        for (int i = 0; i < 2; i++) {
            int lin = tid + i * 256;
            int r = lin >> 4, c = lin & 15;
            const __nv_bfloat16* g = B + (long)(kt * TBK + r) * ldb + col0 + c * 8;
            cpasync16(sptr(Bs + r * TBN + ((c ^ (r & 7)) << 3)), g);
        }
    }
}

// ---------------------------------------------------------------------------
// Core bf16 tensor-core GEMM body: C[M,N] = A[M,K] @ op(B)
//   TB=false: B is [N,K] row-major -> C = A @ B^T (NT)
//   TB=true : B is [K,N] row-major -> C = A @ B   (NN)
// MODE 0: bf16 C = acc + bias[col]
// MODE 1: fp32 C = acc                  (scores; scale folded into softmax)
// MODE 2: bf16 C = acc                  (PV)
// MODE 3: fp32 C = X + beta[0]*(acc + bias[col])
// 128x128x32 tiles, 256 threads (8 warps 2x4), warp tile 64x32,
// 3-stage cp.async pipeline, swizzled smem, ldmatrix + mma.m16n8k16.
// ---------------------------------------------------------------------------
template<int MODE, bool TB>
__device__ __forceinline__ void gemm_body(
    const __nv_bfloat16* __restrict__ A, const __nv_bfloat16* __restrict__ B,
    const float* __restrict__ bias, void* __restrict__ Cv,
    int K, int lda, int ldb, int ldc,
    const float* __restrict__ X, const float* __restrict__ beta,
    char* dsm, int row0, int col0)
{
    __nv_bfloat16* As = reinterpret_cast<__nv_bfloat16*>(dsm);
    __nv_bfloat16* Bs = As + NSTAGE * STAGE_ELEMS;

    const int tid  = threadIdx.x;
    const int lane = tid & 31;
    const int wid  = tid >> 5;
    const int wm   = (wid & 1) * 64;
    const int wn   = (wid >> 1) * 32;

    float acc[4][4][4];
#pragma unroll
    for (int i = 0; i < 4; i++)
#pragma unroll
        for (int j = 0; j < 4; j++)
#pragma unroll
            for (int k = 0; k < 4; k++) acc[i][j][k] = 0.f;

    const int ntiles = K / TBK;

    issue_tile<TB>(A, B, As, Bs, row0, col0, lda, ldb, 0, tid);
    cp_commit();
    issue_tile<TB>(A, B, As + STAGE_ELEMS, Bs + STAGE_ELEMS, row0, col0, lda, ldb, 1, tid);
    cp_commit();

    for (int kt = 0; kt < ntiles; kt++) {
        const int stg = kt % NSTAGE;
        if (kt + 2 < ntiles) {
            const int ps = (kt + 2) % NSTAGE;
            issue_tile<TB>(A, B, As + ps * STAGE_ELEMS, Bs + ps * STAGE_ELEMS,
                           row0, col0, lda, ldb, kt + 2, tid);
        }
        cp_commit();
        cp_wait2();
        __syncthreads();

        const __nv_bfloat16* Asb = As + stg * STAGE_ELEMS;
        const __nv_bfloat16* Bsb = Bs + stg * STAGE_ELEMS;

#pragma unroll
        for (int ks = 0; ks < 2; ks++) {
            unsigned aF[4][4], bF[4][2];
#pragma unroll
            for (int mi = 0; mi < 4; mi++) {
                int r = wm + mi * 16 + (lane & 15);
                int c = ks * 2 + (lane >> 4);
                ldsm4(aF[mi][0], aF[mi][1], aF[mi][2], aF[mi][3],
                      sptr(Asb + r * TBK + ((c ^ ((r >> 1) & 3)) << 3)));
            }
            if (!TB) {
#pragma unroll
                for (int nt = 0; nt < 2; nt++) {
                    int r = wn + nt * 16 + (lane & 15);
                    int c = ks * 2 + (lane >> 4);
                    unsigned r0, r1, r2, r3;
                    ldsm4(r0, r1, r2, r3,
                          sptr(Bsb + r * TBK + ((c ^ ((r >> 1) & 3)) << 3)));
                    bF[nt * 2 + 0][0] = r0; bF[nt * 2 + 0][1] = r2;
                    bF[nt * 2 + 1][0] = r1; bF[nt * 2 + 1][1] = r3;
                }
            } else {
#pragma unroll
                for (int nt = 0; nt < 2; nt++) {
                    int r = ks * 16 + (lane & 15);
                    int c = (wn >> 3) + nt * 2 + (lane >> 4);
                    unsigned r0, r1, r2, r3;
                    ldsm4t(r0, r1, r2, r3,
                           sptr(Bsb + r * TBN + ((c ^ (r & 7)) << 3)));
                    bF[nt * 2 + 0][0] = r0; bF[nt * 2 + 0][1] = r1;
                    bF[nt * 2 + 1][0] = r2; bF[nt * 2 + 1][1] = r3;
                }
            }
#pragma unroll
            for (int mi = 0; mi < 4; mi++)
#pragma unroll
                for (int nj = 0; nj < 4; nj++)
                    mma16816(acc[mi][nj], aF[mi], bF[nj]);
        }
        __syncthreads();
    }

    // ---------------- epilogue ----------------
    const int rg = lane >> 2;
    const int t  = lane & 3;
    float betav = 0.f;
    if (MODE == 3) betav = beta[0];

#pragma unroll
    for (int mi = 0; mi < 4; mi++) {
#pragma unroll
        for (int nj = 0; nj < 4; nj++) {
            const int r = row0 + wm + mi * 16 + rg;
            const int c = col0 + wn + nj * 8 + t * 2;
            const float d0 = acc[mi][nj][0];
            const float d1 = acc[mi][nj][1];
            const float d2 = acc[mi][nj][2];
            const float d3 = acc[mi][nj][3];

            if (MODE == 0) {
                __nv_bfloat16* C = reinterpret_cast<__nv_bfloat16*>(Cv);
                const float2 bb = *reinterpret_cast<const float2*>(bias + c);
                *reinterpret_cast<__nv_bfloat162*>(C + (long)r * ldc + c) =
                    __floats2bfloat162_rn(d0 + bb.x, d1 + bb.y);
                *reinterpret_cast<__nv_bfloat162*>(C + (long)(r + 8) * ldc + c) =
                    __floats2bfloat162_rn(d2 + bb.x, d3 + bb.y);
            } else if (MODE == 1) {
                float* C = reinterpret_cast<float*>(Cv);
                *reinterpret_cast<float2*>(C + (long)r * ldc + c) = make_float2(d0, d1);
                *reinterpret_cast<float2*>(C + (long)(r + 8) * ldc + c) = make_float2(d2, d3);
            } else if (MODE == 2) {
                __nv_bfloat16* C = reinterpret_cast<__nv_bfloat16*>(Cv);
                *reinterpret_cast<__nv_bfloat162*>(C + (long)r * ldc + c) =
                    __floats2bfloat162_rn(d0, d1);
                *reinterpret_cast<__nv_bfloat162*>(C + (long)(r + 8) * ldc + c) =
                    __floats2bfloat162_rn(d2, d3);
            } else {
                float* C = reinterpret_cast<float*>(Cv);
                const float2 bb = *reinterpret_cast<const float2*>(bias + c);
                const float2 x0 = *reinterpret_cast<const float2*>(X + (long)r * ldc + c);
                const float2 x1 = *reinterpret_cast<const float2*>(X + (long)(r + 8) * ldc + c);
                *reinterpret_cast<float2*>(C + (long)r * ldc + c) =
                    make_float2(x0.x + betav * (d0 + bb.x), x0.y + betav * (d1 + bb.y));
                *reinterpret_cast<float2*>(C + (long)(r + 8) * ldc + c) =
                    make_float2(x1.x + betav * (d2 + bb.x), x1.y + betav * (d3 + bb.y));
            }
        }
    }
}

// ---------------- QKV fused: grid.z in {0,1,2} selects W/bias/C ----------------
__global__ __launch_bounds__(256, 2)
void hgemm_qkv(const __nv_bfloat16* __restrict__ A,
               const __nv_bfloat16* __restrict__ W0, const __nv_bfloat16* __restrict__ W1,
               const __nv_bfloat16* __restrict__ W2,
               const float* __restrict__ b0, const float* __restrict__ b1,
               const float* __restrict__ b2,
               __nv_bfloat16* __restrict__ C0, __nv_bfloat16* __restrict__ C1,
               __nv_bfloat16* __restrict__ C2)
{
    extern __shared__ char dsm[];
    const int z = blockIdx.z;
    const __nv_bfloat16* W = (z == 0) ? W0 : (z == 1) ? W1 : W2;
    const float* bias      = (z == 0) ? b0 : (z == 1) ? b1 : b2;
    __nv_bfloat16* C       = (z == 0) ? C0 : (z == 1) ? C1 : C2;
    gemm_body<0, false>(A, W, bias, C, DIM, DIM, DIM, DIM, nullptr, nullptr,
                        dsm, blockIdx.y * TBM, blockIdx.x * TBN);
}

// ---------------- generic batched GEMM (z = group) ----------------
template<int MODE, bool TB>
__global__ __launch_bounds__(256, 2)
void hgemm(const __nv_bfloat16* __restrict__ A, const __nv_bfloat16* __restrict__ B,
           const float* __restrict__ bias, void* __restrict__ Cv,
           int K, int lda, int ldb, int ldc,
           long sA, long sB, long sC,
           const float* __restrict__ X, const float* __restrict__ beta)
{
    extern __shared__ char dsm[];
    const int bz = blockIdx.z;
    void* C;
    if (MODE == 1 || MODE == 3) C = (void*)((float*)Cv + bz * sC);
    else                        C = (void*)((__nv_bfloat16*)Cv + bz * sC);
    gemm_body<MODE, TB>(A + bz * sA, B + bz * sB, bias, C,
                        K, lda, ldb, ldc, X, beta,
                        dsm, blockIdx.y * TBM, blockIdx.x * TBN);
}

// ---------------- merged fp32 -> bf16 converts ----------------
__global__ __launch_bounds__(256)
void conv_all(const float* __restrict__ x,
              const float* __restrict__ wq, const float* __restrict__ wk,
              const float* __restrict__ wv, const float* __restrict__ wo,
              __nv_bfloat16* __restrict__ xb,
              __nv_bfloat16* __restrict__ wqb, __nv_bfloat16* __restrict__ wkb,
              __nv_bfloat16* __restrict__ wvb, __nv_bfloat16* __restrict__ wob)
{
    const long NX = (long)NG * DIM;
    const long W  = (long)DIM * DIM;
    long i = ((long)blockIdx.x * 256 + threadIdx.x) * 4;
    if (i >= NX + 4 * W) return;
    const float* src;
    __nv_bfloat16* dst;
    long off;
    if (i < NX) { src = x; dst = xb; off = i; }
    else {
        long j = i - NX;
        int w = (int)(j / W);
        off = j - (long)w * W;
        src = (w == 0) ? wq : (w == 1) ? wk : (w == 2) ? wv : wo;
        dst = (w == 0) ? wqb : (w == 1) ? wkb : (w == 2) ? wvb : wob;
    }
    float4 v = *reinterpret_cast<const float4*>(src + off);
    *reinterpret_cast<__nv_bfloat162*>(dst + off)     = __floats2bfloat162_rn(v.x, v.y);
    *reinterpret_cast<__nv_bfloat162*>(dst + off + 2) = __floats2bfloat162_rn(v.z, v.w);
}

// ---------------- masked softmax (scale folded), fp32 -> bf16 ----------------
__global__ __launch_bounds__(128)
void softmax_rows(const float* __restrict__ S, __nv_bfloat16* __restrict__ P, float scale)
{
    const int row = blockIdx.x;
    const int grp = row >> 9;
    const int r   = row & 511;
    const float* p = S + ((long)grp << 18) + ((long)r << 9);
    __nv_bfloat16* q = P + ((long)grp << 18) + ((long)r << 9);
    const int tid = threadIdx.x;
    const int w = tid >> 5;
    const int l = tid & 31;
    const int base = tid * 4;

    float4 v4 = *reinterpret_cast<const float4*>(p + base);
    float v0 = v4.x * scale, v1 = v4.y * scale, v2 = v4.z * scale, v3 = v4.w * scale;
    if (base + 0 == r) v0 = -INFINITY;
    if (base + 1 == r) v1 = -INFINITY;
    if (base + 2 == r) v2 = -INFINITY;
    if (base + 3 == r) v3 = -INFINITY;

    float mx = fmaxf(fmaxf(v0, v1), fmaxf(v2, v3));
#pragma unroll
    for (int o = 16; o; o >>= 1) mx = fmaxf(mx, __shfl_xor_sync(0xffffffffu, mx, o));
    __shared__ float sred[8];
    if (l == 0) sred[w] = mx;
    __syncthreads();
    mx = fmaxf(fmaxf(sred[0], sred[1]), fmaxf(sred[2], sred[3]));

    v0 = __expf(v0 - mx); v1 = __expf(v1 - mx);
    v2 = __expf(v2 - mx); v3 = __expf(v3 - mx);
    float sum = v0 + v1 + v2 + v3;
#pragma unroll
    for (int o = 16; o; o >>= 1) sum += __shfl_xor_sync(0xffffffffu, sum, o);
    __syncthreads();
    if (l == 0) sred[4 + w] = sum;
    __syncthreads();
    sum = sred[4] + sred[5] + sred[6] + sred[7];
    const float inv = 1.f / sum;

    *reinterpret_cast<__nv_bfloat162*>(q + base)     = __floats2bfloat162_rn(v0 * inv, v1 * inv);
    *reinterpret_cast<__nv_bfloat162*>(q + base + 2) = __floats2bfloat162_rn(v2 * inv, v3 * inv);
}

// ---------------------------------------------------------------------------
// Launcher. Inputs: x, batch(unused), Wq,bq, Wk,bk, Wv,bv, Wo,bo, beta.
// ---------------------------------------------------------------------------
extern "C" void kernel_launch(void* const* d_in, const int* in_sizes, int n_in,
                              void* d_out, int out_size)
{
    (void)in_sizes; (void)n_in; (void)out_size;
    const float* x    = (const float*)d_in[0];
    const float* Wq   = (const float*)d_in[2];
    const float* bq   = (const float*)d_in[3];
    const float* Wk   = (const float*)d_in[4];
    const float* bk   = (const float*)d_in[5];
    const float* Wv   = (const float*)d_in[6];
    const float* bv   = (const float*)d_in[7];
    const float* Wo   = (const float*)d_in[8];
    const float* bo   = (const float*)d_in[9];
    const float* beta = (const float*)d_in[10];
    float* out = (float*)d_out;

    __nv_bfloat16 *xb, *Wqb, *Wkb, *Wvb, *Wob, *Q, *K, *V, *P, *DYN;
    float *S;
    cudaGetSymbolAddress((void**)&xb,  g_xb);
    cudaGetSymbolAddress((void**)&Wqb, g_Wqb);
    cudaGetSymbolAddress((void**)&Wkb, g_Wkb);
    cudaGetSymbolAddress((void**)&Wvb, g_Wvb);
    cudaGetSymbolAddress((void**)&Wob, g_Wob);
    cudaGetSymbolAddress((void**)&Q,   g_Q);
    cudaGetSymbolAddress((void**)&K,   g_K);
    cudaGetSymbolAddress((void**)&V,   g_V);
    cudaGetSymbolAddress((void**)&S,   g_S);
    cudaGetSymbolAddress((void**)&P,   g_P);
    cudaGetSymbolAddress((void**)&DYN, g_DYN);

    static bool attr_done = false;
    if (!attr_done) {
        cudaFuncSetAttribute(hgemm_qkv,       cudaFuncAttributeMaxDynamicSharedMemorySize, SMEM_BYTES);
        cudaFuncSetAttribute(hgemm<1, false>, cudaFuncAttributeMaxDynamicSharedMemorySize, SMEM_BYTES);
        cudaFuncSetAttribute(hgemm<2, true>,  cudaFuncAttributeMaxDynamicSharedMemorySize, SMEM_BYTES);
        cudaFuncSetAttribute(hgemm<3, false>, cudaFuncAttributeMaxDynamicSharedMemorySize, SMEM_BYTES);
        attr_done = true;
    }

    const float scale = 1.0f / sqrtf((float)DIM);
    const dim3 blk(256);

    // converts (one launch)
    {
        long total4 = ((long)NG * DIM + 4L * DIM * DIM) / 4;
        int blocks = (int)((total4 + 255) / 256);
        conv_all<<<blocks, 256>>>(x, Wq, Wk, Wv, Wo, xb, Wqb, Wkb, Wvb, Wob);
    }

    // Q/K/V projections in one launch (z selects): bf16 [8192,768] @ [768,768]^T + bias
    hgemm_qkv<<<dim3(6, 64, 3), blk, SMEM_BYTES>>>(xb, Wqb, Wkb, Wvb, bq, bk, bv, Q, K, V);

    // Per-group scores: S_g = Q_g @ K_g^T (unscaled fp32, batched z=16)
    hgemm<1, false><<<dim3(4, 4, BGRP), blk, SMEM_BYTES>>>(
        Q, K, nullptr, S, DIM, DIM, DIM, GS,
        (long)GS * DIM, (long)GS * DIM, (long)GS * GS, nullptr, nullptr);

    // Masked softmax (scale folded): fp32 S -> bf16 P
    softmax_rows<<<NG, 128>>>(S, P, scale);

    // Per-group P @ V -> bf16 DYN (NN via ldmatrix.trans, batched z=16)
    hgemm<2, true><<<dim3(6, 4, BGRP), blk, SMEM_BYTES>>>(
        P, V, nullptr, DYN, GS, GS, DIM, DIM,
        (long)GS * GS, (long)GS * DIM, (long)GS * DIM, nullptr, nullptr);

    // Output projection + residual: out = x + beta*(DYN @ Wo^T + bo) (fp32)
    hgemm<3, false><<<dim3(6, 64, 1), blk, SMEM_BYTES>>>(
        DYN, Wob, bo, out, DIM, DIM, DIM, DIM, 0, 0, 0, x, beta);
}

// round 7
// speedup vs baseline: 7.5663x; 1.1332x over previous
#include <cuda_runtime.h>
#include <cuda_bf16.h>
#include <cstdint>
#include <cmath>

#define NG    8192
#define BGRP  16
#define GS    512
#define DIM   768

// tile sizes
#define TBM 128
#define TBN 128
#define TBK 64
#define NSTAGE 3
#define STAGE_ELEMS (TBM * TBK)                   // per-operand per-stage bf16 elems (8192)
#define SMEM_BYTES (NSTAGE * 2 * STAGE_ELEMS * 2) // 98304 bytes

// ---------------- scratch (device globals; no allocs allowed) ----------------
__device__ __nv_bfloat16 g_xb [NG * DIM];
__device__ __nv_bfloat16 g_Wqb[DIM * DIM];
__device__ __nv_bfloat16 g_Wkb[DIM * DIM];
__device__ __nv_bfloat16 g_Wvb[DIM * DIM];
__device__ __nv_bfloat16 g_Wob[DIM * DIM];
__device__ __nv_bfloat16 g_Q  [NG * DIM];
__device__ __nv_bfloat16 g_K  [NG * DIM];
__device__ __nv_bfloat16 g_V  [NG * DIM];
__device__ float         g_S  [BGRP * GS * GS];
__device__ __nv_bfloat16 g_P  [BGRP * GS * GS];
__device__ __nv_bfloat16 g_DYN[NG * DIM];

// ---------------- helpers ----------------
__device__ __forceinline__ unsigned sptr(const void* p) {
    return (unsigned)__cvta_generic_to_shared(p);
}
__device__ __forceinline__ void cpasync16(unsigned s, const void* g) {
    asm volatile("cp.async.cg.shared.global [%0], [%1], 16;\n" :: "r"(s), "l"(g));
}
__device__ __forceinline__ void cp_commit() {
    asm volatile("cp.async.commit_group;\n" ::: "memory");
}
__device__ __forceinline__ void cp_wait2() {
    asm volatile("cp.async.wait_group 2;\n" ::: "memory");
}
__device__ __forceinline__ void ldsm4(unsigned& r0, unsigned& r1, unsigned& r2, unsigned& r3, unsigned a) {
    asm volatile("ldmatrix.sync.aligned.m8n8.x4.shared.b16 {%0,%1,%2,%3}, [%4];\n"
                 : "=r"(r0), "=r"(r1), "=r"(r2), "=r"(r3) : "r"(a));
}
__device__ __forceinline__ void ldsm4t(unsigned& r0, unsigned& r1, unsigned& r2, unsigned& r3, unsigned a) {
    asm volatile("ldmatrix.sync.aligned.m8n8.x4.trans.shared.b16 {%0,%1,%2,%3}, [%4];\n"
                 : "=r"(r0), "=r"(r1), "=r"(r2), "=r"(r3) : "r"(a));
}
__device__ __forceinline__ void mma16816(float* d, const unsigned* a, const unsigned* b) {
    asm volatile(
        "mma.sync.aligned.m16n8k16.row.col.f32.bf16.bf16.f32 "
        "{%0,%1,%2,%3}, {%4,%5,%6,%7}, {%8,%9}, {%0,%1,%2,%3};\n"
        : "+f"(d[0]), "+f"(d[1]), "+f"(d[2]), "+f"(d[3])
        : "r"(a[0]), "r"(a[1]), "r"(a[2]), "r"(a[3]), "r"(b[0]), "r"(b[1]));
}

// ---- cp.async tile issue into stage buffers (BK=64 -> 128B rows, 8-way XOR swizzle) ----
template<bool TB>
__device__ __forceinline__ void issue_tile(
    const __nv_bfloat16* __restrict__ A, const __nv_bfloat16* __restrict__ B,
    __nv_bfloat16* As, __nv_bfloat16* Bs,
    int row0, int col0, int lda, int ldb, int kt, int tid)
{
    // A tile: [128 rows x 64 k], 8 chunks (16B) per row, 1024 chunks, 4 per thread
#pragma unroll
    for (int i = 0; i < 4; i++) {
        int lin = tid + i * 256;
        int r = lin >> 3, c = lin & 7;
        const __nv_bfloat16* g = A + (long)(row0 + r) * lda + kt * TBK + c * 8;
        cpasync16(sptr(As + r * TBK + ((c ^ (r & 7)) << 3)), g);
    }
    if (!TB) {
        // B tile: [128 rows x 64 k], k-contiguous, same layout as A
#pragma unroll
        for (int i = 0; i < 4; i++) {
            int lin = tid + i * 256;
            int r = lin >> 3, c = lin & 7;
            const __nv_bfloat16* g = B + (long)(col0 + r) * ldb + kt * TBK + c * 8;
            cpasync16(sptr(Bs + r * TBK + ((c ^ (r & 7)) << 3)), g);
        }
    } else {
        // B tile: [64 k-rows x 128 n], n-contiguous; 16 chunks per row
#pragma unroll
        for (int i = 0; i < 4; i++) {
            int lin = tid + i * 256;
            int r = lin >> 4, c = lin & 15;
            const __nv_bfloat16* g = B + (long)(kt * TBK + r) * ldb + col0 + c * 8;
            cpasync16(sptr(Bs + r * TBN + ((c ^ (r & 7)) << 3)), g);
        }
    }
}

// ---------------------------------------------------------------------------
// Core bf16 tensor-core GEMM body: C[M,N] = A[M,K] @ op(B)
//   TB=false: B is [N,K] row-major -> C = A @ B^T (NT)
//   TB=true : B is [K,N] row-major -> C = A @ B   (NN)
// MODE 0: bf16 C = acc + bias[col]
// MODE 1: fp32 C = acc                  (scores; scale folded into softmax)
// MODE 2: bf16 C = acc                  (PV)
// MODE 3: fp32 C = X + beta[0]*(acc + bias[col])
// 128x128x64 tiles, 256 threads (8 warps 2x4), warp tile 64x32,
// 3-stage cp.async pipeline, SW128 smem, ldmatrix + mma.m16n8k16.
// ---------------------------------------------------------------------------
template<int MODE, bool TB>
__device__ __forceinline__ void gemm_body(
    const __nv_bfloat16* __restrict__ A, const __nv_bfloat16* __restrict__ B,
    const float* __restrict__ bias, void* __restrict__ Cv,
    int K, int lda, int ldb, int ldc,
    const float* __restrict__ X, const float* __restrict__ beta,
    char* dsm, int row0, int col0)
{
    __nv_bfloat16* As = reinterpret_cast<__nv_bfloat16*>(dsm);
    __nv_bfloat16* Bs = As + NSTAGE * STAGE_ELEMS;

    const int tid  = threadIdx.x;
    const int lane = tid & 31;
    const int wid  = tid >> 5;
    const int wm   = (wid & 1) * 64;
    const int wn   = (wid >> 1) * 32;

    float acc[4][4][4];
#pragma unroll
    for (int i = 0; i < 4; i++)
#pragma unroll
        for (int j = 0; j < 4; j++)
#pragma unroll
            for (int k = 0; k < 4; k++) acc[i][j][k] = 0.f;

    const int ntiles = K / TBK;

    issue_tile<TB>(A, B, As, Bs, row0, col0, lda, ldb, 0, tid);
    cp_commit();
    issue_tile<TB>(A, B, As + STAGE_ELEMS, Bs + STAGE_ELEMS, row0, col0, lda, ldb, 1, tid);
    cp_commit();

    for (int kt = 0; kt < ntiles; kt++) {
        const int stg = kt % NSTAGE;
        if (kt + 2 < ntiles) {
            const int ps = (kt + 2) % NSTAGE;
            issue_tile<TB>(A, B, As + ps * STAGE_ELEMS, Bs + ps * STAGE_ELEMS,
                           row0, col0, lda, ldb, kt + 2, tid);
        }
        cp_commit();
        cp_wait2();
        __syncthreads();

        const __nv_bfloat16* Asb = As + stg * STAGE_ELEMS;
        const __nv_bfloat16* Bsb = Bs + stg * STAGE_ELEMS;

#pragma unroll
        for (int ks = 0; ks < 4; ks++) {          // four k16 steps per BK=64
            unsigned aF[4][4], bF[4][2];
#pragma unroll
            for (int mi = 0; mi < 4; mi++) {
                int r = wm + mi * 16 + (lane & 15);
                int c = ks * 2 + (lane >> 4);
                ldsm4(aF[mi][0], aF[mi][1], aF[mi][2], aF[mi][3],
                      sptr(Asb + r * TBK + ((c ^ (r & 7)) << 3)));
            }
            if (!TB) {
#pragma unroll
                for (int nt = 0; nt < 2; nt++) {
                    int r = wn + nt * 16 + (lane & 15);
                    int c = ks * 2 + (lane >> 4);
                    unsigned r0, r1, r2, r3;
                    ldsm4(r0, r1, r2, r3,
                          sptr(Bsb + r * TBK + ((c ^ (r & 7)) << 3)));
                    bF[nt * 2 + 0][0] = r0; bF[nt * 2 + 0][1] = r2;
                    bF[nt * 2 + 1][0] = r1; bF[nt * 2 + 1][1] = r3;
                }
            } else {
#pragma unroll
                for (int nt = 0; nt < 2; nt++) {
                    int r = ks * 16 + (lane & 15);
                    int c = (wn >> 3) + nt * 2 + (lane >> 4);
                    unsigned r0, r1, r2, r3;
                    ldsm4t(r0, r1, r2, r3,
                           sptr(Bsb + r * TBN + ((c ^ (r & 7)) << 3)));
                    bF[nt * 2 + 0][0] = r0; bF[nt * 2 + 0][1] = r1;
                    bF[nt * 2 + 1][0] = r2; bF[nt * 2 + 1][1] = r3;
                }
            }
#pragma unroll
            for (int mi = 0; mi < 4; mi++)
#pragma unroll
                for (int nj = 0; nj < 4; nj++)
                    mma16816(acc[mi][nj], aF[mi], bF[nj]);
        }
        __syncthreads();
    }

    // ---------------- epilogue ----------------
    const int rg = lane >> 2;
    const int t  = lane & 3;
    float betav = 0.f;
    if (MODE == 3) betav = beta[0];

#pragma unroll
    for (int mi = 0; mi < 4; mi++) {
#pragma unroll
        for (int nj = 0; nj < 4; nj++) {
            const int r = row0 + wm + mi * 16 + rg;
            const int c = col0 + wn + nj * 8 + t * 2;
            const float d0 = acc[mi][nj][0];
            const float d1 = acc[mi][nj][1];
            const float d2 = acc[mi][nj][2];
            const float d3 = acc[mi][nj][3];

            if (MODE == 0) {
                __nv_bfloat16* C = reinterpret_cast<__nv_bfloat16*>(Cv);
                const float2 bb = *reinterpret_cast<const float2*>(bias + c);
                *reinterpret_cast<__nv_bfloat162*>(C + (long)r * ldc + c) =
                    __floats2bfloat162_rn(d0 + bb.x, d1 + bb.y);
                *reinterpret_cast<__nv_bfloat162*>(C + (long)(r + 8) * ldc + c) =
                    __floats2bfloat162_rn(d2 + bb.x, d3 + bb.y);
            } else if (MODE == 1) {
                float* C = reinterpret_cast<float*>(Cv);
                *reinterpret_cast<float2*>(C + (long)r * ldc + c) = make_float2(d0, d1);
                *reinterpret_cast<float2*>(C + (long)(r + 8) * ldc + c) = make_float2(d2, d3);
            } else if (MODE == 2) {
                __nv_bfloat16* C = reinterpret_cast<__nv_bfloat16*>(Cv);
                *reinterpret_cast<__nv_bfloat162*>(C + (long)r * ldc + c) =
                    __floats2bfloat162_rn(d0, d1);
                *reinterpret_cast<__nv_bfloat162*>(C + (long)(r + 8) * ldc + c) =
                    __floats2bfloat162_rn(d2, d3);
            } else {
                float* C = reinterpret_cast<float*>(Cv);
                const float2 bb = *reinterpret_cast<const float2*>(bias + c);
                const float2 x0 = *reinterpret_cast<const float2*>(X + (long)r * ldc + c);
                const float2 x1 = *reinterpret_cast<const float2*>(X + (long)(r + 8) * ldc + c);
                *reinterpret_cast<float2*>(C + (long)r * ldc + c) =
                    make_float2(x0.x + betav * (d0 + bb.x), x0.y + betav * (d1 + bb.y));
                *reinterpret_cast<float2*>(C + (long)(r + 8) * ldc + c) =
                    make_float2(x1.x + betav * (d2 + bb.x), x1.y + betav * (d3 + bb.y));
            }
        }
    }
}

// ---------------- QKV fused: grid.z in {0,1,2} selects W/bias/C ----------------
__global__ __launch_bounds__(256, 2)
void hgemm_qkv(const __nv_bfloat16* __restrict__ A,
               const __nv_bfloat16* __restrict__ W0, const __nv_bfloat16* __restrict__ W1,
               const __nv_bfloat16* __restrict__ W2,
               const float* __restrict__ b0, const float* __restrict__ b1,
               const float* __restrict__ b2,
               __nv_bfloat16* __restrict__ C0, __nv_bfloat16* __restrict__ C1,
               __nv_bfloat16* __restrict__ C2)
{
    extern __shared__ char dsm[];
    const int z = blockIdx.z;
    const __nv_bfloat16* W = (z == 0) ? W0 : (z == 1) ? W1 : W2;
    const float* bias      = (z == 0) ? b0 : (z == 1) ? b1 : b2;
    __nv_bfloat16* C       = (z == 0) ? C0 : (z == 1) ? C1 : C2;
    gemm_body<0, false>(A, W, bias, C, DIM, DIM, DIM, DIM, nullptr, nullptr,
                        dsm, blockIdx.y * TBM, blockIdx.x * TBN);
}

// ---------------- generic batched GEMM (z = group) ----------------
template<int MODE, bool TB>
__global__ __launch_bounds__(256, 2)
void hgemm(const __nv_bfloat16* __restrict__ A, const __nv_bfloat16* __restrict__ B,
           const float* __restrict__ bias, void* __restrict__ Cv,
           int K, int lda, int ldb, int ldc,
           long sA, long sB, long sC,
           const float* __restrict__ X, const float* __restrict__ beta)
{
    extern __shared__ char dsm[];
    const int bz = blockIdx.z;
    void* C;
    if (MODE == 1 || MODE == 3) C = (void*)((float*)Cv + bz * sC);
    else                        C = (void*)((__nv_bfloat16*)Cv + bz * sC);
    gemm_body<MODE, TB>(A + bz * sA, B + bz * sB, bias, C,
                        K, lda, ldb, ldc, X, beta,
                        dsm, blockIdx.y * TBM, blockIdx.x * TBN);
}

// ---------------- merged fp32 -> bf16 converts ----------------
__global__ __launch_bounds__(256)
void conv_all(const float* __restrict__ x,
              const float* __restrict__ wq, const float* __restrict__ wk,
              const float* __restrict__ wv, const float* __restrict__ wo,
              __nv_bfloat16* __restrict__ xb,
              __nv_bfloat16* __restrict__ wqb, __nv_bfloat16* __restrict__ wkb,
              __nv_bfloat16* __restrict__ wvb, __nv_bfloat16* __restrict__ wob)
{
    const long NX = (long)NG * DIM;
    const long W  = (long)DIM * DIM;
    long i = ((long)blockIdx.x * 256 + threadIdx.x) * 4;
    if (i >= NX + 4 * W) return;
    const float* src;
    __nv_bfloat16* dst;
    long off;
    if (i < NX) { src = x; dst = xb; off = i; }
    else {
        long j = i - NX;
        int w = (int)(j / W);
        off = j - (long)w * W;
        src = (w == 0) ? wq : (w == 1) ? wk : (w == 2) ? wv : wo;
        dst = (w == 0) ? wqb : (w == 1) ? wkb : (w == 2) ? wvb : wob;
    }
    float4 v = *reinterpret_cast<const float4*>(src + off);
    *reinterpret_cast<__nv_bfloat162*>(dst + off)     = __floats2bfloat162_rn(v.x, v.y);
    *reinterpret_cast<__nv_bfloat162*>(dst + off + 2) = __floats2bfloat162_rn(v.z, v.w);
}

// ---------------- masked softmax (scale folded), warp-per-row ----------------
// 256 threads = 8 warps = 8 rows per CTA. 16 elems/lane, shuffle-only reductions.
__global__ __launch_bounds__(256)
void softmax_rows(const float* __restrict__ S, __nv_bfloat16* __restrict__ P, float scale)
{
    const int row  = blockIdx.x * 8 + (threadIdx.x >> 5);
    const int lane = threadIdx.x & 31;
    const int grp  = row >> 9;
    const int r    = row & 511;
    const float* p = S + ((long)grp << 18) + ((long)r << 9);
    __nv_bfloat16* q = P + ((long)grp << 18) + ((long)r << 9);

    float v[16];
    float mx = -INFINITY;
#pragma unroll
    for (int i = 0; i < 4; i++) {
        const int col = i * 128 + lane * 4;
        float4 v4 = *reinterpret_cast<const float4*>(p + col);
        v[i * 4 + 0] = (col + 0 == r) ? -INFINITY : v4.x * scale;
        v[i * 4 + 1] = (col + 1 == r) ? -INFINITY : v4.y * scale;
        v[i * 4 + 2] = (col + 2 == r) ? -INFINITY : v4.z * scale;
        v[i * 4 + 3] = (col + 3 == r) ? -INFINITY : v4.w * scale;
#pragma unroll
        for (int j = 0; j < 4; j++) mx = fmaxf(mx, v[i * 4 + j]);
    }
#pragma unroll
    for (int o = 16; o; o >>= 1) mx = fmaxf(mx, __shfl_xor_sync(0xffffffffu, mx, o));

    float sum = 0.f;
#pragma unroll
    for (int i = 0; i < 16; i++) { v[i] = __expf(v[i] - mx); sum += v[i]; }
#pragma unroll
    for (int o = 16; o; o >>= 1) sum += __shfl_xor_sync(0xffffffffu, sum, o);
    const float inv = 1.f / sum;

#pragma unroll
    for (int i = 0; i < 4; i++) {
        const int col = i * 128 + lane * 4;
        *reinterpret_cast<__nv_bfloat162*>(q + col) =
            __floats2bfloat162_rn(v[i * 4 + 0] * inv, v[i * 4 + 1] * inv);
        *reinterpret_cast<__nv_bfloat162*>(q + col + 2) =
            __floats2bfloat162_rn(v[i * 4 + 2] * inv, v[i * 4 + 3] * inv);
    }
}

// ---------------------------------------------------------------------------
// Launcher. Inputs: x, batch(unused), Wq,bq, Wk,bk, Wv,bv, Wo,bo, beta.
// ---------------------------------------------------------------------------
extern "C" void kernel_launch(void* const* d_in, const int* in_sizes, int n_in,
                              void* d_out, int out_size)
{
    (void)in_sizes; (void)n_in; (void)out_size;
    const float* x    = (const float*)d_in[0];
    const float* Wq   = (const float*)d_in[2];
    const float* bq   = (const float*)d_in[3];
    const float* Wk   = (const float*)d_in[4];
    const float* bk   = (const float*)d_in[5];
    const float* Wv   = (const float*)d_in[6];
    const float* bv   = (const float*)d_in[7];
    const float* Wo   = (const float*)d_in[8];
    const float* bo   = (const float*)d_in[9];
    const float* beta = (const float*)d_in[10];
    float* out = (float*)d_out;

    __nv_bfloat16 *xb, *Wqb, *Wkb, *Wvb, *Wob, *Q, *K, *V, *P, *DYN;
    float *S;
    cudaGetSymbolAddress((void**)&xb,  g_xb);
    cudaGetSymbolAddress((void**)&Wqb, g_Wqb);
    cudaGetSymbolAddress((void**)&Wkb, g_Wkb);
    cudaGetSymbolAddress((void**)&Wvb, g_Wvb);
    cudaGetSymbolAddress((void**)&Wob, g_Wob);
    cudaGetSymbolAddress((void**)&Q,   g_Q);
    cudaGetSymbolAddress((void**)&K,   g_K);
    cudaGetSymbolAddress((void**)&V,   g_V);
    cudaGetSymbolAddress((void**)&S,   g_S);
    cudaGetSymbolAddress((void**)&P,   g_P);
    cudaGetSymbolAddress((void**)&DYN, g_DYN);

    static bool attr_done = false;
    if (!attr_done) {
        cudaFuncSetAttribute(hgemm_qkv,       cudaFuncAttributeMaxDynamicSharedMemorySize, SMEM_BYTES);
        cudaFuncSetAttribute(hgemm<1, false>, cudaFuncAttributeMaxDynamicSharedMemorySize, SMEM_BYTES);
        cudaFuncSetAttribute(hgemm<2, true>,  cudaFuncAttributeMaxDynamicSharedMemorySize, SMEM_BYTES);
        cudaFuncSetAttribute(hgemm<3, false>, cudaFuncAttributeMaxDynamicSharedMemorySize, SMEM_BYTES);
        attr_done = true;
    }

    const float scale = 1.0f / sqrtf((float)DIM);
    const dim3 blk(256);

    // converts (one launch)
    {
        long total4 = ((long)NG * DIM + 4L * DIM * DIM) / 4;
        int blocks = (int)((total4 + 255) / 256);
        conv_all<<<blocks, 256>>>(x, Wq, Wk, Wv, Wo, xb, Wqb, Wkb, Wvb, Wob);
    }

    // Q/K/V projections in one launch (z selects): bf16 [8192,768] @ [768,768]^T + bias
    hgemm_qkv<<<dim3(6, 64, 3), blk, SMEM_BYTES>>>(xb, Wqb, Wkb, Wvb, bq, bk, bv, Q, K, V);

    // Per-group scores: S_g = Q_g @ K_g^T (unscaled fp32, batched z=16)
    hgemm<1, false><<<dim3(4, 4, BGRP), blk, SMEM_BYTES>>>(
        Q, K, nullptr, S, DIM, DIM, DIM, GS,
        (long)GS * DIM, (long)GS * DIM, (long)GS * GS, nullptr, nullptr);

    // Masked softmax (scale folded): fp32 S -> bf16 P, warp-per-row
    softmax_rows<<<NG / 8, 256>>>(S, P, scale);

    // Per-group P @ V -> bf16 DYN (NN via ldmatrix.trans, batched z=16)
    hgemm<2, true><<<dim3(6, 4, BGRP), blk, SMEM_BYTES>>>(
        P, V, nullptr, DYN, GS, GS, DIM, DIM,
        (long)GS * GS, (long)GS * DIM, (long)GS * DIM, nullptr, nullptr);

    // Output projection + residual: out = x + beta*(DYN @ Wo^T + bo) (fp32)
    hgemm<3, false><<<dim3(6, 64, 1), blk, SMEM_BYTES>>>(
        DYN, Wob, bo, out, DIM, DIM, DIM, DIM, 0, 0, 0, x, beta);
}